// round 6
// baseline (speedup 1.0000x reference)
#include <cuda_runtime.h>

typedef unsigned long long u64;

#define BATCH   262144
#define DD      6
#define HH      100
#define TT      8
#define NPAIRS  (BATCH/2)
#define NQUADS  (BATCH/4)
#define NELEM   (BATCH*DD)
#define NBLOCKS 148
#define NTHREADS 256
#define TOTTHR  (NBLOCKS*NTHREADS)
#define NSLOTS  72
#define MAXSTEPS 64

// ---- device scratch (no allocation allowed) ----
__device__ u64   g_y [2][DD][NPAIRS];
__device__ u64   g_fy[2][DD][NPAIRS];
__device__ float g_part[NSLOTS][NBLOCKS][2];
__device__ unsigned g_count;

__global__ void ode_init_kernel() { g_count = 0u; }

// ---- packed f32x2 helpers (sm_103a) ----
__device__ __forceinline__ u64 F2FMA(u64 a, u64 b, u64 c) {
    u64 d; asm("fma.rn.f32x2 %0,%1,%2,%3;" : "=l"(d) : "l"(a), "l"(b), "l"(c)); return d;
}
__device__ __forceinline__ u64 F2MUL(u64 a, u64 b) {
    u64 d; asm("mul.rn.f32x2 %0,%1,%2;" : "=l"(d) : "l"(a), "l"(b)); return d;
}
__device__ __forceinline__ u64 F2ADD(u64 a, u64 b) {
    u64 d; asm("add.rn.f32x2 %0,%1,%2;" : "=l"(d) : "l"(a), "l"(b)); return d;
}
__device__ __forceinline__ u64 PACK2(float lo, float hi) {
    u64 d; asm("mov.b64 %0,{%1,%2};" : "=l"(d) : "f"(lo), "f"(hi)); return d;
}
__device__ __forceinline__ float2 UNPACK2(u64 v) {
    float2 r; asm("mov.b64 {%0,%1},%2;" : "=f"(r.x), "=f"(r.y) : "l"(v)); return r;
}
__device__ __forceinline__ u64 DUP(float s) { return PACK2(s, s); }

// hardware tanh (sm_75+): 1 MUFU op
__device__ __forceinline__ float TANHA(float x) {
    float r; asm("tanh.approx.f32 %0,%1;" : "=f"(r) : "f"(x)); return r;
}
__device__ __forceinline__ u64 TANH2(u64 a) {
    float2 x = UNPACK2(a);
    return PACK2(TANHA(x.x), TANHA(x.y));
}

// ---- MLP on 4 rows (two packed pairs); split layer-1 chain for latency ----
// sW1 rows: 8 u64 per j = [w1*6 | b1 | pad]. sW2 rows: 6 u64 per j.
__device__ __forceinline__ void mlp4(const u64* __restrict__ sW1, const u64* __restrict__ sW2,
                                     const u64* __restrict__ sb2,
                                     const u64 yin[12], u64 out[12]) {
#pragma unroll
    for (int d = 0; d < DD; d++) { out[d] = sb2[d]; out[d+6] = sb2[d]; }
#pragma unroll 2
    for (int j = 0; j < HH; j++) {
        const ulonglong2* r = (const ulonglong2*)(sW1 + j*8);
        ulonglong2 wa = r[0], wb = r[1], wc = r[2], wd = r[3];
        // two 3-deep partial sums per row-pair (depth 16 instead of 24)
        u64 sA1 = F2FMA(wa.x, yin[0], wd.x);
        u64 sB1 = F2FMA(wa.x, yin[6], wd.x);
        sA1 = F2FMA(wa.y, yin[1], sA1);  sB1 = F2FMA(wa.y, yin[7],  sB1);
        sA1 = F2FMA(wb.x, yin[2], sA1);  sB1 = F2FMA(wb.x, yin[8],  sB1);
        u64 sA2 = F2MUL(wb.y, yin[3]);   u64 sB2 = F2MUL(wb.y, yin[9]);
        sA2 = F2FMA(wc.x, yin[4], sA2);  sB2 = F2FMA(wc.x, yin[10], sB2);
        sA2 = F2FMA(wc.y, yin[5], sA2);  sB2 = F2FMA(wc.y, yin[11], sB2);
        u64 tA = TANH2(F2ADD(sA1, sA2));
        u64 tB = TANH2(F2ADD(sB1, sB2));
        const ulonglong2* q = (const ulonglong2*)(sW2 + j*6);
        ulonglong2 va = q[0], vb = q[1], vc = q[2];
        out[0] = F2FMA(va.x, tA, out[0]); out[6]  = F2FMA(va.x, tB, out[6]);
        out[1] = F2FMA(va.y, tA, out[1]); out[7]  = F2FMA(va.y, tB, out[7]);
        out[2] = F2FMA(vb.x, tA, out[2]); out[8]  = F2FMA(vb.x, tB, out[8]);
        out[3] = F2FMA(vb.y, tA, out[3]); out[9]  = F2FMA(vb.y, tB, out[9]);
        out[4] = F2FMA(vc.x, tA, out[4]); out[10] = F2FMA(vc.x, tB, out[10]);
        out[5] = F2FMA(vc.y, tA, out[5]); out[11] = F2FMA(vc.y, tB, out[11]);
    }
}

// scalar-coefficient axpy: 2 scalar FFMA per element, no duplicated coef regs
__device__ __forceinline__ void axpy12(u64 t[12], const u64 k[12], float c) {
#pragma unroll
    for (int d = 0; d < 12; d++) {
        float2 tv = UNPACK2(t[d]), kv = UNPACK2(k[d]);
        t[d] = PACK2(fmaf(c, kv.x, tv.x), fmaf(c, kv.y, tv.y));
    }
}
__device__ __forceinline__ void setax12(u64 t[12], const u64 y[12], const u64 k[12], float c) {
#pragma unroll
    for (int d = 0; d < 12; d++) {
        float2 yv = UNPACK2(y[d]), kv = UNPACK2(k[d]);
        t[d] = PACK2(fmaf(c, kv.x, yv.x), fmaf(c, kv.y, yv.y));
    }
}
__device__ __forceinline__ void setmul12(u64 t[12], const u64 k[12], float c) {
#pragma unroll
    for (int d = 0; d < 12; d++) {
        float2 kv = UNPACK2(k[d]);
        t[d] = PACK2(c * kv.x, c * kv.y);
    }
}

// ---- deterministic grid-wide sum of two floats; slot must increase per call ----
__device__ float2 reduce2(float a, float b, int slot) {
    __shared__ float swA[NTHREADS/32], swB[NTHREADS/32];
    __shared__ float2 bc;
    unsigned lane = threadIdx.x & 31, wid = threadIdx.x >> 5;
#pragma unroll
    for (int o = 16; o; o >>= 1) {
        a += __shfl_xor_sync(0xffffffffu, a, o);
        b += __shfl_xor_sync(0xffffffffu, b, o);
    }
    if (lane == 0) { swA[wid] = a; swB[wid] = b; }
    __syncthreads();
    if (threadIdx.x == 0) {
        float sa = 0.f, sb = 0.f;
#pragma unroll
        for (int i = 0; i < NTHREADS/32; i++) { sa += swA[i]; sb += swB[i]; }
        g_part[slot][blockIdx.x][0] = sa;
        g_part[slot][blockIdx.x][1] = sb;
        __threadfence();
        atomicAdd(&g_count, 1u);
        unsigned target = (unsigned)(slot + 1) * NBLOCKS;
        while (atomicAdd(&g_count, 0u) < target) __nanosleep(64);
        __threadfence();
        float ta = 0.f, tb = 0.f;
        for (int i = 0; i < NBLOCKS; i++) {
            ta += __ldcg(&g_part[slot][i][0]);
            tb += __ldcg(&g_part[slot][i][1]);
        }
        bc = make_float2(ta, tb);
    }
    __syncthreads();
    return bc;
}

__device__ __forceinline__ void err_acc(float& acc, u64 e, u64 yv, u64 yn) {
    float2 ef = UNPACK2(e), y0 = UNPACK2(yv), y1 = UNPACK2(yn);
    float s0 = fmaf(1e-7f, fmaxf(fabsf(y0.x), fabsf(y1.x)), 1e-9f);
    float s1 = fmaf(1e-7f, fmaxf(fabsf(y0.y), fabsf(y1.y)), 1e-9f);
    float q0 = __fdividef(ef.x, s0), q1 = __fdividef(ef.y, s1);
    acc = fmaf(q0, q0, acc); acc = fmaf(q1, q1, acc);
}

__global__ void __launch_bounds__(NTHREADS)
ode_kernel(const float* __restrict__ in_seq, const float* __restrict__ W1,
           const float* __restrict__ b1, const float* __restrict__ W2,
           const float* __restrict__ b2, const float* __restrict__ Wl,
           const float* __restrict__ bl, float* __restrict__ out) {
    const float A21f = 0.2f;
    const float A31f = 3.f/40.f,  A32f = 9.f/40.f;
    const float A41f = 44.f/45.f, A42f = -56.f/15.f, A43f = 32.f/9.f;
    const float A51f = 19372.f/6561.f, A52f = -25360.f/2187.f, A53f = 64448.f/6561.f, A54f = -212.f/729.f;
    const float A61f = 9017.f/3168.f,  A62f = -355.f/33.f,     A63f = 46732.f/5247.f,
                A64f = 49.f/176.f,     A65f = -5103.f/18656.f;
    const float B1f = 35.f/384.f, B3f = 500.f/1113.f, B4f = 125.f/192.f, B5f = -2187.f/6784.f, B6f = 11.f/84.f;
    const float E1f = 71.f/57600.f, E3f = -71.f/16695.f, E4f = 71.f/1920.f,
                E5f = -17253.f/339200.f, E6f = 22.f/525.f, E7f = -1.f/40.f;
    const float INVN = 1.0f / (float)NELEM;

    __shared__ __align__(16) u64 sW1[HH*8];
    __shared__ __align__(16) u64 sW2[HH*6];
    __shared__ __align__(16) u64 sb2[DD];

    const int tid  = threadIdx.x;
    const int gtid = blockIdx.x * NTHREADS + tid;

    for (int i = tid; i < HH; i += NTHREADS) {
#pragma unroll
        for (int d = 0; d < DD; d++) {
            float w1v = W1[i*DD + d];   sW1[i*8 + d] = PACK2(w1v, w1v);
            float w2v = W2[d*HH + i];   sW2[i*6 + d] = PACK2(w2v, w2v);
        }
        float bv = b1[i];
        sW1[i*8 + 6] = PACK2(bv, bv);
        sW1[i*8 + 7] = 0ull;
    }
    if (tid < DD) { float v = b2[tid]; sb2[tid] = PACK2(v, v); }
    __syncthreads();

    int slot = 0;

    // ---- Pass A: y0 = input_seq[:,-1,:], f0 = f(y0), accumulate d0,d1 ----
    float a0 = 0.f, a1 = 0.f;
    for (int q = gtid; q < NQUADS; q += TOTTHR) {
        u64 y[12], f[12];
#pragma unroll
        for (int h = 0; h < 2; h++) {
            const float* r0 = in_seq + (size_t)(4*q + 2*h) * (TT*DD) + (TT-1)*DD;
            const float* r1 = r0 + TT*DD;
#pragma unroll
            for (int d = 0; d < DD; d++) y[6*h + d] = PACK2(r0[d], r1[d]);
        }
        mlp4(sW1, sW2, sb2, y, f);
#pragma unroll
        for (int h = 0; h < 2; h++) {
            int p = 2*q + h;
#pragma unroll
            for (int d = 0; d < DD; d++) {
                g_y[0][d][p]  = y[6*h + d];
                g_fy[0][d][p] = f[6*h + d];
                float2 yv = UNPACK2(y[6*h + d]), fv = UNPACK2(f[6*h + d]);
                float s0 = fmaf(1e-7f, fabsf(yv.x), 1e-9f);
                float s1 = fmaf(1e-7f, fabsf(yv.y), 1e-9f);
                float q0 = __fdividef(yv.x, s0), q1 = __fdividef(yv.y, s1);
                a0 = fmaf(q0, q0, a0); a0 = fmaf(q1, q1, a0);
                q0 = __fdividef(fv.x, s0); q1 = __fdividef(fv.y, s1);
                a1 = fmaf(q0, q0, a1); a1 = fmaf(q1, q1, a1);
            }
        }
    }
    float2 s01 = reduce2(a0, a1, slot++);
    float d0 = sqrtf(s01.x * INVN), d1 = sqrtf(s01.y * INVN);
    float h0 = ((d0 < 1e-5f) || (d1 < 1e-5f)) ? 1e-6f : 0.01f * d0 / fmaxf(d1, 1e-12f);

    // ---- Pass B: d2 = rms((f(y0+h0*f0)-f0)/scale)/h0 ----
    float a2 = 0.f;
    for (int q = gtid; q < NQUADS; q += TOTTHR) {
        u64 y[12], f[12], y1v[12], f1v[12];
#pragma unroll
        for (int h = 0; h < 2; h++) {
            int p = 2*q + h;
#pragma unroll
            for (int d = 0; d < DD; d++) { y[6*h+d] = g_y[0][d][p]; f[6*h+d] = g_fy[0][d][p]; }
        }
        setax12(y1v, y, f, h0);
        mlp4(sW1, sW2, sb2, y1v, f1v);
#pragma unroll
        for (int d = 0; d < 12; d++) {
            float2 yv = UNPACK2(y[d]), fv = UNPACK2(f[d]), gv = UNPACK2(f1v[d]);
            float s0 = fmaf(1e-7f, fabsf(yv.x), 1e-9f);
            float s1 = fmaf(1e-7f, fabsf(yv.y), 1e-9f);
            float q0 = __fdividef(gv.x - fv.x, s0), q1 = __fdividef(gv.y - fv.y, s1);
            a2 = fmaf(q0, q0, a2); a2 = fmaf(q1, q1, a2);
        }
    }
    float2 s2 = reduce2(a2, 0.f, slot++);
    float d2 = sqrtf(s2.x * INVN) / h0;
    float dm = fmaxf(d1, d2);
    float h1 = (dm <= 1e-15f) ? fmaxf(1e-6f, h0 * 1e-3f)
                              : powf(0.01f / fmaxf(dm, 1e-15f), 0.2f);
    float h = fminf(fminf(100.f * h0, h1), 1.0f);

    // ---- adaptive step loop with early exit ----
    float t = 0.f;
    int cur = 0;
    for (int it = 0; it < MAXSTEPS; it++) {
        if (t >= 1.0f - 1e-12f) break;
        float hc = fminf(h, 1.0f - t);
        float acc = 0.f;
        for (int q = gtid; q < NQUADS; q += TOTTHR) {
            u64 y[12], k1[12], k2[12], k3[12], k4[12], k5[12];
            u64 tmp[12], yp[12], e[12];
#pragma unroll
            for (int h2 = 0; h2 < 2; h2++) {
                int p = 2*q + h2;
#pragma unroll
                for (int d = 0; d < DD; d++) { y[6*h2+d] = g_y[cur][d][p]; k1[6*h2+d] = g_fy[cur][d][p]; }
            }
            // stage 2
            setax12(tmp, y, k1, hc*A21f);
            mlp4(sW1, sW2, sb2, tmp, k2);
            // stage 3
            setax12(tmp, y, k1, hc*A31f); axpy12(tmp, k2, hc*A32f);
            mlp4(sW1, sW2, sb2, tmp, k3);
            // stage 4
            setax12(tmp, y, k1, hc*A41f); axpy12(tmp, k2, hc*A42f); axpy12(tmp, k3, hc*A43f);
            mlp4(sW1, sW2, sb2, tmp, k4);
            // stage 5
            setax12(tmp, y, k1, hc*A51f); axpy12(tmp, k2, hc*A52f); axpy12(tmp, k3, hc*A53f); axpy12(tmp, k4, hc*A54f);
            mlp4(sW1, sW2, sb2, tmp, k5);
            // stage-6 input (k2 dies here)
            setax12(tmp, y, k1, hc*A61f); axpy12(tmp, k2, hc*A62f); axpy12(tmp, k3, hc*A63f);
            axpy12(tmp, k4, hc*A64f); axpy12(tmp, k5, hc*A65f);
            // partial y_new / err BEFORE stage-6 MLP (k1,k3,k4,k5 die here)
            setax12(yp, y, k1, hc*B1f); axpy12(yp, k3, hc*B3f); axpy12(yp, k4, hc*B4f); axpy12(yp, k5, hc*B5f);
            setmul12(e, k1, hc*E1f);
            axpy12(e, k3, hc*E3f); axpy12(e, k4, hc*E4f); axpy12(e, k5, hc*E5f);
            // stage 6
            mlp4(sW1, sW2, sb2, tmp, k2);            // k2 = k6
            axpy12(yp, k2, hc*B6f);                   // y_new complete
            axpy12(e,  k2, hc*E6f);
            // k7 = f(y_new)
            mlp4(sW1, sW2, sb2, yp, k3);              // k3 = k7
            axpy12(e, k3, hc*E7f);
#pragma unroll
            for (int h2 = 0; h2 < 2; h2++) {
                int p = 2*q + h2;
#pragma unroll
                for (int d = 0; d < DD; d++) {
                    g_y [cur^1][d][p] = yp[6*h2+d];
                    g_fy[cur^1][d][p] = k3[6*h2+d];
                    err_acc(acc, e[6*h2+d], y[6*h2+d], yp[6*h2+d]);
                }
            }
        }
        float2 se = reduce2(acc, 0.f, slot++);
        float en = sqrtf(se.x * INVN);
        float pw = exp2f(-0.2f * log2f(fmaxf(en, 1e-10f)));
        float factor = fminf(fmaxf(0.9f * pw, 0.2f), 10.0f);
        if (en <= 1.0f) { t += hc; cur ^= 1; }
        h = hc * factor;
    }

    // ---- output: out[b] = dot(yT[b], Wl) + bl ----
    float wl[DD];
#pragma unroll
    for (int d = 0; d < DD; d++) wl[d] = Wl[d];
    float blv = bl[0];
    for (int q = gtid; q < NQUADS; q += TOTTHR) {
#pragma unroll
        for (int h2 = 0; h2 < 2; h2++) {
            int p = 2*q + h2;
            float o0 = blv, o1 = blv;
#pragma unroll
            for (int d = 0; d < DD; d++) {
                float2 yv = UNPACK2(g_y[cur][d][p]);
                o0 = fmaf(yv.x, wl[d], o0);
                o1 = fmaf(yv.y, wl[d], o1);
            }
            out[2*p]   = o0;
            out[2*p+1] = o1;
        }
    }
}

extern "C" void kernel_launch(void* const* d_in, const int* in_sizes, int n_in,
                              void* d_out, int out_size) {
    const float* in_seq = (const float*)d_in[0];
    const float* W1 = (const float*)d_in[1];
    const float* b1 = (const float*)d_in[2];
    const float* W2 = (const float*)d_in[3];
    const float* b2 = (const float*)d_in[4];
    const float* Wl = (const float*)d_in[5];
    const float* bl = (const float*)d_in[6];
    float* out = (float*)d_out;
    ode_init_kernel<<<1, 1>>>();
    ode_kernel<<<NBLOCKS, NTHREADS>>>(in_seq, W1, b1, W2, b2, Wl, bl, out);
}

// round 7
// speedup vs baseline: 1.5597x; 1.5597x over previous
#include <cuda_runtime.h>

typedef unsigned long long u64;

#define BATCH   262144
#define DD      6
#define HH      100
#define TT      8
#define NPAIRS  (BATCH/2)
#define NQUADS  (BATCH/4)
#define NELEM   (BATCH*DD)
#define NBLOCKS 148
#define NTHREADS 256
#define TOTTHR  (NBLOCKS*NTHREADS)
#define MAXSTEPS 64
#define NSLOTS  72

// dynamic smem layout (u64 units)
#define SW1_OFF 0
#define SW2_OFF (HH*8)
#define SB2_OFF (SW1_OFF + HH*8 + HH*6)
#define SY_OFF  (SB2_OFF + 8)
#define SE_OFF  (SY_OFF + 12*NTHREADS)
#define SMEM_U64 (SE_OFF + 12*NTHREADS)
#define SMEM_BYTES (SMEM_U64*8)

// ---- device scratch (no allocation allowed) ----
__device__ u64   g_y [2][DD][NPAIRS];
__device__ u64   g_fy[2][DD][NPAIRS];
__device__ float g_part[NSLOTS][NBLOCKS][2];
__device__ unsigned g_count;

__global__ void ode_init_kernel() { g_count = 0u; }

// ---- packed f32x2 helpers (sm_103a) ----
__device__ __forceinline__ u64 F2FMA(u64 a, u64 b, u64 c) {
    u64 d; asm("fma.rn.f32x2 %0,%1,%2,%3;" : "=l"(d) : "l"(a), "l"(b), "l"(c)); return d;
}
__device__ __forceinline__ u64 F2MUL(u64 a, u64 b) {
    u64 d; asm("mul.rn.f32x2 %0,%1,%2;" : "=l"(d) : "l"(a), "l"(b)); return d;
}
__device__ __forceinline__ u64 PACK2(float lo, float hi) {
    u64 d; asm("mov.b64 %0,{%1,%2};" : "=l"(d) : "f"(lo), "f"(hi)); return d;
}
__device__ __forceinline__ float2 UNPACK2(u64 v) {
    float2 r; asm("mov.b64 {%0,%1},%2;" : "=f"(r.x), "=f"(r.y) : "l"(v)); return r;
}
__device__ __forceinline__ u64 DUP(float s) { return PACK2(s, s); }

// hardware tanh (sm_75+): 1 MUFU op
__device__ __forceinline__ float TANHA(float x) {
    float r; asm("tanh.approx.f32 %0,%1;" : "=f"(r) : "f"(x)); return r;
}
__device__ __forceinline__ u64 TANH2(u64 a) {
    float2 x = UNPACK2(a);
    return PACK2(TANHA(x.x), TANHA(x.y));
}

// ---- MLP on 4 rows — ARITHMETIC IDENTICAL TO R5 (do not touch; trajectory-stable) ----
__device__ __forceinline__ void mlp4(const u64* __restrict__ sW1, const u64* __restrict__ sW2,
                                     const u64* __restrict__ sb2,
                                     const u64 yin[12], u64 out[12]) {
#pragma unroll
    for (int d = 0; d < DD; d++) { out[d] = sb2[d]; out[d+6] = sb2[d]; }
#pragma unroll 2
    for (int j = 0; j < HH; j++) {
        const ulonglong2* r = (const ulonglong2*)(sW1 + j*8);
        ulonglong2 wa = r[0], wb = r[1], wc = r[2], wd = r[3];
        u64 aA = wd.x, aB = wd.x;                       // b1[j]
        aA = F2FMA(wa.x, yin[0], aA); aB = F2FMA(wa.x, yin[6],  aB);
        aA = F2FMA(wa.y, yin[1], aA); aB = F2FMA(wa.y, yin[7],  aB);
        aA = F2FMA(wb.x, yin[2], aA); aB = F2FMA(wb.x, yin[8],  aB);
        aA = F2FMA(wb.y, yin[3], aA); aB = F2FMA(wb.y, yin[9],  aB);
        aA = F2FMA(wc.x, yin[4], aA); aB = F2FMA(wc.x, yin[10], aB);
        aA = F2FMA(wc.y, yin[5], aA); aB = F2FMA(wc.y, yin[11], aB);
        u64 tA = TANH2(aA), tB = TANH2(aB);
        const ulonglong2* q = (const ulonglong2*)(sW2 + j*6);
        ulonglong2 va = q[0], vb = q[1], vc = q[2];
        out[0] = F2FMA(va.x, tA, out[0]); out[6]  = F2FMA(va.x, tB, out[6]);
        out[1] = F2FMA(va.y, tA, out[1]); out[7]  = F2FMA(va.y, tB, out[7]);
        out[2] = F2FMA(vb.x, tA, out[2]); out[8]  = F2FMA(vb.x, tB, out[8]);
        out[3] = F2FMA(vb.y, tA, out[3]); out[9]  = F2FMA(vb.y, tB, out[9]);
        out[4] = F2FMA(vc.x, tA, out[4]); out[10] = F2FMA(vc.x, tB, out[10]);
        out[5] = F2FMA(vc.y, tA, out[5]); out[11] = F2FMA(vc.y, tB, out[11]);
    }
}

// packed axpy; coef DUP'd inline (transient) — same F2FMA stream as R5
__device__ __forceinline__ void axpy12(u64 t[12], const u64 k[12], float c) {
    u64 cc = DUP(c);
#pragma unroll
    for (int d = 0; d < 12; d++) t[d] = F2FMA(cc, k[d], t[d]);
}
__device__ __forceinline__ void setax12(u64 t[12], const u64 y[12], const u64 k[12], float c) {
    u64 cc = DUP(c);
#pragma unroll
    for (int d = 0; d < 12; d++) t[d] = F2FMA(cc, k[d], y[d]);
}
// t = y(smem) + c*k  — y values bit-identical, just sourced from smem
__device__ __forceinline__ void setaxY(u64 t[12], const u64* sy, const u64 k[12], float c) {
    u64 cc = DUP(c);
#pragma unroll
    for (int d = 0; d < 12; d++) t[d] = F2FMA(cc, k[d], sy[d*NTHREADS]);
}
// e ops in smem (in-place)
__device__ __forceinline__ void setmulE(u64* se, const u64 k[12], float c) {
    u64 cc = DUP(c);
#pragma unroll
    for (int d = 0; d < 12; d++) se[d*NTHREADS] = F2MUL(cc, k[d]);
}
__device__ __forceinline__ void axpyE(u64* se, const u64 k[12], float c) {
    u64 cc = DUP(c);
#pragma unroll
    for (int d = 0; d < 12; d++) se[d*NTHREADS] = F2FMA(cc, k[d], se[d*NTHREADS]);
}

// ---- deterministic grid-wide sum of two floats; slot must increase per call ----
__device__ float2 reduce2(float a, float b, int slot) {
    __shared__ float swA[NTHREADS/32], swB[NTHREADS/32];
    __shared__ float2 bc;
    unsigned lane = threadIdx.x & 31, wid = threadIdx.x >> 5;
#pragma unroll
    for (int o = 16; o; o >>= 1) {
        a += __shfl_xor_sync(0xffffffffu, a, o);
        b += __shfl_xor_sync(0xffffffffu, b, o);
    }
    if (lane == 0) { swA[wid] = a; swB[wid] = b; }
    __syncthreads();
    if (threadIdx.x == 0) {
        float sa = 0.f, sb = 0.f;
#pragma unroll
        for (int i = 0; i < NTHREADS/32; i++) { sa += swA[i]; sb += swB[i]; }
        g_part[slot][blockIdx.x][0] = sa;
        g_part[slot][blockIdx.x][1] = sb;
        __threadfence();
        atomicAdd(&g_count, 1u);
        unsigned target = (unsigned)(slot + 1) * NBLOCKS;
        while (atomicAdd(&g_count, 0u) < target) __nanosleep(64);
        __threadfence();
        float ta = 0.f, tb = 0.f;
        for (int i = 0; i < NBLOCKS; i++) {
            ta += __ldcg(&g_part[slot][i][0]);
            tb += __ldcg(&g_part[slot][i][1]);
        }
        bc = make_float2(ta, tb);
    }
    __syncthreads();
    return bc;
}

__device__ __forceinline__ void err_acc(float& acc, u64 e, u64 yv, u64 yn) {
    float2 ef = UNPACK2(e), y0 = UNPACK2(yv), y1 = UNPACK2(yn);
    float s0 = fmaf(1e-7f, fmaxf(fabsf(y0.x), fabsf(y1.x)), 1e-9f);
    float s1 = fmaf(1e-7f, fmaxf(fabsf(y0.y), fabsf(y1.y)), 1e-9f);
    float q0 = __fdividef(ef.x, s0), q1 = __fdividef(ef.y, s1);
    acc = fmaf(q0, q0, acc); acc = fmaf(q1, q1, acc);
}

__global__ void __launch_bounds__(NTHREADS)
ode_kernel(const float* __restrict__ in_seq, const float* __restrict__ W1,
           const float* __restrict__ b1, const float* __restrict__ W2,
           const float* __restrict__ b2, const float* __restrict__ Wl,
           const float* __restrict__ bl, float* __restrict__ out) {
    const float A21f = 0.2f;
    const float A31f = 3.f/40.f,  A32f = 9.f/40.f;
    const float A41f = 44.f/45.f, A42f = -56.f/15.f, A43f = 32.f/9.f;
    const float A51f = 19372.f/6561.f, A52f = -25360.f/2187.f, A53f = 64448.f/6561.f, A54f = -212.f/729.f;
    const float A61f = 9017.f/3168.f,  A62f = -355.f/33.f,     A63f = 46732.f/5247.f,
                A64f = 49.f/176.f,     A65f = -5103.f/18656.f;
    const float B1f = 35.f/384.f, B3f = 500.f/1113.f, B4f = 125.f/192.f, B5f = -2187.f/6784.f, B6f = 11.f/84.f;
    const float E1f = 71.f/57600.f, E3f = -71.f/16695.f, E4f = 71.f/1920.f,
                E5f = -17253.f/339200.f, E6f = 22.f/525.f, E7f = -1.f/40.f;
    const float INVN = 1.0f / (float)NELEM;

    extern __shared__ __align__(16) u64 dsm[];
    u64* sW1 = dsm + SW1_OFF;
    u64* sW2 = dsm + SW2_OFF;
    u64* sb2 = dsm + SB2_OFF;

    const int tid  = threadIdx.x;
    const int gtid = blockIdx.x * NTHREADS + tid;
    u64* sY = dsm + SY_OFF + tid;   // stride NTHREADS per d
    u64* sE = dsm + SE_OFF + tid;

    for (int i = tid; i < HH; i += NTHREADS) {
#pragma unroll
        for (int d = 0; d < DD; d++) {
            float w1v = W1[i*DD + d];   sW1[i*8 + d] = PACK2(w1v, w1v);
            float w2v = W2[d*HH + i];   sW2[i*6 + d] = PACK2(w2v, w2v);
        }
        float bv = b1[i];
        sW1[i*8 + 6] = PACK2(bv, bv);
        sW1[i*8 + 7] = 0ull;
    }
    if (tid < DD) { float v = b2[tid]; sb2[tid] = PACK2(v, v); }
    __syncthreads();

    int slot = 0;

    // ---- Pass A: y0 = input_seq[:,-1,:], f0 = f(y0), accumulate d0,d1 ----
    float a0 = 0.f, a1 = 0.f;
    for (int q = gtid; q < NQUADS; q += TOTTHR) {
        u64 y[12], f[12];
#pragma unroll
        for (int h = 0; h < 2; h++) {
            const float* r0 = in_seq + (size_t)(4*q + 2*h) * (TT*DD) + (TT-1)*DD;
            const float* r1 = r0 + TT*DD;
#pragma unroll
            for (int d = 0; d < DD; d++) y[6*h + d] = PACK2(r0[d], r1[d]);
        }
        mlp4(sW1, sW2, sb2, y, f);
#pragma unroll
        for (int h = 0; h < 2; h++) {
            int p = 2*q + h;
#pragma unroll
            for (int d = 0; d < DD; d++) {
                g_y[0][d][p]  = y[6*h + d];
                g_fy[0][d][p] = f[6*h + d];
                float2 yv = UNPACK2(y[6*h + d]), fv = UNPACK2(f[6*h + d]);
                float s0 = fmaf(1e-7f, fabsf(yv.x), 1e-9f);
                float s1 = fmaf(1e-7f, fabsf(yv.y), 1e-9f);
                float q0 = __fdividef(yv.x, s0), q1 = __fdividef(yv.y, s1);
                a0 = fmaf(q0, q0, a0); a0 = fmaf(q1, q1, a0);
                q0 = __fdividef(fv.x, s0); q1 = __fdividef(fv.y, s1);
                a1 = fmaf(q0, q0, a1); a1 = fmaf(q1, q1, a1);
            }
        }
    }
    float2 s01 = reduce2(a0, a1, slot++);
    float d0 = sqrtf(s01.x * INVN), d1 = sqrtf(s01.y * INVN);
    float h0 = ((d0 < 1e-5f) || (d1 < 1e-5f)) ? 1e-6f : 0.01f * d0 / fmaxf(d1, 1e-12f);

    // ---- Pass B: d2 = rms((f(y0+h0*f0)-f0)/scale)/h0 ----
    float a2 = 0.f;
    for (int q = gtid; q < NQUADS; q += TOTTHR) {
        u64 y[12], f[12], y1v[12], f1v[12];
#pragma unroll
        for (int h = 0; h < 2; h++) {
            int p = 2*q + h;
#pragma unroll
            for (int d = 0; d < DD; d++) { y[6*h+d] = g_y[0][d][p]; f[6*h+d] = g_fy[0][d][p]; }
        }
        setax12(y1v, y, f, h0);
        mlp4(sW1, sW2, sb2, y1v, f1v);
#pragma unroll
        for (int d = 0; d < 12; d++) {
            float2 yv = UNPACK2(y[d]), fv = UNPACK2(f[d]), gv = UNPACK2(f1v[d]);
            float s0 = fmaf(1e-7f, fabsf(yv.x), 1e-9f);
            float s1 = fmaf(1e-7f, fabsf(yv.y), 1e-9f);
            float q0 = __fdividef(gv.x - fv.x, s0), q1 = __fdividef(gv.y - fv.y, s1);
            a2 = fmaf(q0, q0, a2); a2 = fmaf(q1, q1, a2);
        }
    }
    float2 s2 = reduce2(a2, 0.f, slot++);
    float d2 = sqrtf(s2.x * INVN) / h0;
    float dm = fmaxf(d1, d2);
    float h1 = (dm <= 1e-15f) ? fmaxf(1e-6f, h0 * 1e-3f)
                              : powf(0.01f / fmaxf(dm, 1e-15f), 0.2f);
    float h = fminf(fminf(100.f * h0, h1), 1.0f);

    // ---- adaptive step loop with early exit ----
    float t = 0.f;
    int cur = 0;
    for (int it = 0; it < MAXSTEPS; it++) {
        if (t >= 1.0f - 1e-12f) break;
        float hc = fminf(h, 1.0f - t);
        float acc = 0.f;
        for (int q = gtid; q < NQUADS; q += TOTTHR) {
            u64 k1[12], k2[12], k3[12], k4[12], k5[12];
            u64 tmp[12], yp[12];
            // load y -> smem, k1 -> regs
#pragma unroll
            for (int h2 = 0; h2 < 2; h2++) {
                int p = 2*q + h2;
#pragma unroll
                for (int d = 0; d < DD; d++) {
                    sY[(6*h2+d)*NTHREADS] = g_y[cur][d][p];
                    k1[6*h2+d] = g_fy[cur][d][p];
                }
            }
            // stage 2
            setaxY(tmp, sY, k1, hc*A21f);
            mlp4(sW1, sW2, sb2, tmp, k2);
            // stage 3
            setaxY(tmp, sY, k1, hc*A31f); axpy12(tmp, k2, hc*A32f);
            mlp4(sW1, sW2, sb2, tmp, k3);
            // stage 4
            setaxY(tmp, sY, k1, hc*A41f); axpy12(tmp, k2, hc*A42f); axpy12(tmp, k3, hc*A43f);
            mlp4(sW1, sW2, sb2, tmp, k4);
            // stage 5
            setaxY(tmp, sY, k1, hc*A51f); axpy12(tmp, k2, hc*A52f); axpy12(tmp, k3, hc*A53f); axpy12(tmp, k4, hc*A54f);
            mlp4(sW1, sW2, sb2, tmp, k5);
            // stage-6 input (k2 dies here)
            setaxY(tmp, sY, k1, hc*A61f); axpy12(tmp, k2, hc*A62f); axpy12(tmp, k3, hc*A63f);
            axpy12(tmp, k4, hc*A64f); axpy12(tmp, k5, hc*A65f);
            // partial y_new / err BEFORE stage-6 MLP (k1,k3,k4,k5 die here)
            setaxY(yp, sY, k1, hc*B1f); axpy12(yp, k3, hc*B3f); axpy12(yp, k4, hc*B4f); axpy12(yp, k5, hc*B5f);
            setmulE(sE, k1, hc*E1f);
            axpyE(sE, k3, hc*E3f); axpyE(sE, k4, hc*E4f); axpyE(sE, k5, hc*E5f);
            // stage 6
            mlp4(sW1, sW2, sb2, tmp, k2);            // k2 = k6
            axpy12(yp, k2, hc*B6f);                   // y_new complete
            axpyE(sE, k2, hc*E6f);
            // k7 = f(y_new)
            mlp4(sW1, sW2, sb2, yp, k3);              // k3 = k7
            axpyE(sE, k3, hc*E7f);
#pragma unroll
            for (int h2 = 0; h2 < 2; h2++) {
                int p = 2*q + h2;
#pragma unroll
                for (int d = 0; d < DD; d++) {
                    g_y [cur^1][d][p] = yp[6*h2+d];
                    g_fy[cur^1][d][p] = k3[6*h2+d];
                    err_acc(acc, sE[(6*h2+d)*NTHREADS], sY[(6*h2+d)*NTHREADS], yp[6*h2+d]);
                }
            }
        }
        float2 se = reduce2(acc, 0.f, slot++);
        float en = sqrtf(se.x * INVN);
        float pw = exp2f(-0.2f * log2f(fmaxf(en, 1e-10f)));
        float factor = fminf(fmaxf(0.9f * pw, 0.2f), 10.0f);
        if (en <= 1.0f) { t += hc; cur ^= 1; }
        h = hc * factor;
    }

    // ---- output: out[b] = dot(yT[b], Wl) + bl ----
    float wl[DD];
#pragma unroll
    for (int d = 0; d < DD; d++) wl[d] = Wl[d];
    float blv = bl[0];
    for (int q = gtid; q < NQUADS; q += TOTTHR) {
#pragma unroll
        for (int h2 = 0; h2 < 2; h2++) {
            int p = 2*q + h2;
            float o0 = blv, o1 = blv;
#pragma unroll
            for (int d = 0; d < DD; d++) {
                float2 yv = UNPACK2(g_y[cur][d][p]);
                o0 = fmaf(yv.x, wl[d], o0);
                o1 = fmaf(yv.y, wl[d], o1);
            }
            out[2*p]   = o0;
            out[2*p+1] = o1;
        }
    }
}

extern "C" void kernel_launch(void* const* d_in, const int* in_sizes, int n_in,
                              void* d_out, int out_size) {
    const float* in_seq = (const float*)d_in[0];
    const float* W1 = (const float*)d_in[1];
    const float* b1 = (const float*)d_in[2];
    const float* W2 = (const float*)d_in[3];
    const float* b2 = (const float*)d_in[4];
    const float* Wl = (const float*)d_in[5];
    const float* bl = (const float*)d_in[6];
    float* out = (float*)d_out;
    static bool attr_done = false;
    if (!attr_done) {
        cudaFuncSetAttribute(ode_kernel, cudaFuncAttributeMaxDynamicSharedMemorySize, SMEM_BYTES);
        attr_done = true;
    }
    ode_init_kernel<<<1, 1>>>();
    ode_kernel<<<NBLOCKS, NTHREADS, SMEM_BYTES>>>(in_seq, W1, b1, W2, b2, Wl, bl, out);
}